// round 8
// baseline (speedup 1.0000x reference)
#include <cuda_runtime.h>
#include <cuda_fp16.h>
#include <cstdint>

#define DI __device__ __forceinline__

static constexpr int NN  = 8192;
static constexpr int DIM = 256;

// ---------------- scratch (device globals; allocation forbidden) -----------
__device__ __align__(1024) float  g_dis[NN];                // rsqrt(1 + rowsum(adj))
__device__ __align__(1024) __half g_Mth[(size_t)DIM * NN];  // M^T [n][j] fp16 (B-operand layout)
__device__ __align__(1024) __half g_Mrow[(size_t)NN * DIM]; // M   [j][n] fp16 (epilogue layout)
__device__ __align__(1024) __half g_Wh[DIM * DIM];          // W^T fp16

// ---------------- helpers ----------------
DI uint32_t h2_u32(__half2 h) { return *reinterpret_cast<uint32_t*>(&h); }
DI uint32_t packh2(float f0, float f1) {
    __half2 h = __floats2half2_rn(f0, f1);
    return h2_u32(h);
}
DI uint32_t smem_u32(const void* p) {
    uint32_t a;
    asm("{ .reg .u64 t; cvta.to.shared.u64 t, %1; cvt.u32.u64 %0, t; }" : "=r"(a) : "l"(p));
    return a;
}
DI void cp16(uint32_t s, const void* g) {
    asm volatile("cp.async.cg.shared.global [%0], [%1], 16;" :: "r"(s), "l"(g) : "memory");
}
DI void cp_commit() { asm volatile("cp.async.commit_group;" ::: "memory"); }
template <int N> DI void cp_wait() {
    asm volatile("cp.async.wait_group %0;" :: "n"(N) : "memory");
}
DI uint32_t lds32(uint32_t a) {
    uint32_t v;
    asm volatile("ld.shared.b32 %0, [%1];" : "=r"(v) : "r"(a));
    return v;
}
DI void lds_v2f(float& f0, float& f1, uint32_t a) {
    asm volatile("ld.shared.v2.f32 {%0,%1}, [%2];" : "=f"(f0), "=f"(f1) : "r"(a));
}
DI void mma_f16(float* d, const uint32_t* a, const uint32_t* b) {
    asm volatile(
        "mma.sync.aligned.m16n8k16.row.col.f32.f16.f16.f32 "
        "{%0,%1,%2,%3}, {%4,%5,%6,%7}, {%8,%9}, {%0,%1,%2,%3};"
        : "+f"(d[0]), "+f"(d[1]), "+f"(d[2]), "+f"(d[3])
        : "r"(a[0]), "r"(a[1]), "r"(a[2]), "r"(a[3]), "r"(b[0]), "r"(b[1]));
}
DI uint32_t sw128(uint32_t off) { return off ^ ((off >> 3) & 0x70); }

// ---------------- SMEM layout ----------------
// A tile: 128 rows x 64 fp32 = two 128B-row subtiles (k0..31 | k32..63), 32 KB.
// B tile: 128 rows x 64 fp16, 128B rows, 16 KB.  K per stage = 64.
static constexpr int NST      = 4;
static constexpr int A_SUB    = 128 * 128;            // 16 KB per subtile
static constexpr int A_BYTES  = 2 * A_SUB;            // 32 KB
static constexpr int B_BYTES  = 128 * 128;            // 16 KB
static constexpr int STAGE    = A_BYTES + B_BYTES;    // 48 KB
static constexpr int DSMEM    = NST * STAGE;          // 192 KB

// ------ degree: g_dis[i] = rsqrt(1 + rowsum(adj)) (read-only, HBM-bound) ---
__global__ void __launch_bounds__(256) degree_kernel(const float* __restrict__ adj) {
    const int i = blockIdx.x;
    const float4* row = reinterpret_cast<const float4*>(adj + (size_t)i * NN);
    float s = 0.f;
    for (int t = threadIdx.x; t < NN / 4; t += 256) {
        float4 v = row[t];
        s += (v.x + v.y) + (v.z + v.w);
    }
    for (int off = 16; off > 0; off >>= 1) s += __shfl_xor_sync(0xFFFFFFFFu, s, off);
    __shared__ float ws[8];
    if ((threadIdx.x & 31) == 0) ws[threadIdx.x >> 5] = s;
    __syncthreads();
    if (threadIdx.x == 0) {
        float t = 0.f;
        #pragma unroll
        for (int k = 0; k < 8; k++) t += ws[k];
        g_dis[i] = rsqrtf(t + 1.0f);
    }
}

// ---------------- prep: W^T -> fp16 ----------------------------------------
__global__ void __launch_bounds__(256) prep_w_kernel(const float* __restrict__ W) {
    int n = blockIdx.x, k = threadIdx.x;
    g_Wh[n * DIM + k] = __float2half_rn(W[k * DIM + n]);
}

// ---- fp16 mma GEMM, fp32 A converted in-loop: C[128x128]=A[128xK]@B[128xK]^T
// EPI=0: A=x (lda=256, KT=4),   B=g_Wh.  C -> g_Mth (smem-staged) + g_Mrow
// EPI=1: A=adj (lda=8192,KT=128), B=g_Mth. C -> out=relu(dis_i*(acc+M[i][n])+b[n])
template <int EPI>
__global__ void __launch_bounds__(256, 1)
gemm_k(const float* __restrict__ A, int lda, int KT,
       const float* __restrict__ bias, float* __restrict__ out) {
    const __half* __restrict__ B = EPI ? (const __half*)g_Mth : (const __half*)g_Wh;
    const int ldb = EPI ? NN : DIM;

    extern __shared__ char smem[];
    const uint32_t sb = smem_u32(smem);
    const int tid = threadIdx.x, lane = tid & 31, wid = tid >> 5;
    const int wm = wid & 3, wn = wid >> 2;          // warp grid 4(M) x 2(N)
    const size_t mrow0 = (size_t)blockIdx.x * 128;
    const size_t nrow0 = (size_t)blockIdx.y * 128;

    float acc[2][8][4];
    #pragma unroll
    for (int mi = 0; mi < 2; mi++)
        #pragma unroll
        for (int ni = 0; ni < 8; ni++)
            #pragma unroll
            for (int r = 0; r < 4; r++) acc[mi][ni][r] = 0.f;

    // copy geometry: row blocks of 32, chunk = row(128B) x seg(16B)
    const int crow = tid >> 3, cseg = tid & 7;
    const uint32_t sdst = sw128((uint32_t)(crow * 128 + cseg * 16));
    const float*  gA = A + (mrow0 + crow) * (size_t)lda + cseg * 4;   // 4 fp32 / 16B
    const __half* gB = B + (nrow0 + crow) * (size_t)ldb + cseg * 8;   // 8 fp16 / 16B
    const size_t stepA = 32ull * (size_t)lda;
    const size_t stepB = 32ull * (size_t)ldb;

    auto load_stage = [&](int kt) {
        const int s = kt & (NST - 1);
        const uint32_t stA = sb + s * STAGE;
        const uint32_t stB = stA + A_BYTES;
        const int k0 = kt * 64;
        #pragma unroll
        for (int q = 0; q < 4; q++) {   // A subtile 0: k 0..31
            cp16(stA + sdst + q * (32 * 128), gA + k0 + q * stepA);
        }
        #pragma unroll
        for (int q = 0; q < 4; q++) {   // A subtile 1: k 32..63
            cp16(stA + A_SUB + sdst + q * (32 * 128), gA + k0 + 32 + q * stepA);
        }
        #pragma unroll
        for (int q = 0; q < 4; q++) {   // B tile
            cp16(stB + sdst + q * (32 * 128), gB + k0 + q * stepB);
        }
        cp_commit();
    };

    for (int p = 0; p < NST - 1 && p < KT; p++) load_stage(p);

    // fragment geometry (m16n8k16)
    const int arow_base = wm * 32 + (lane >> 2);     // + mi*16, +8
    const int brow_base = wn * 64 + (lane >> 2);     // + ni*8
    const int klane2 = (lane & 3) * 2;               // k element pair base

    for (int kt = 0; kt < KT; kt++) {
        cp_wait<NST - 2>();
        __syncthreads();
        const int s = kt & (NST - 1);
        const uint32_t stA = sb + s * STAGE;
        const uint32_t stB = stA + A_BYTES;

        #pragma unroll
        for (int ks = 0; ks < 4; ks++) {
            const int kb = ks * 32 + (lane & 3) * 4;         // B byte col (fp16)
            uint32_t bf[8][2];
            #pragma unroll
            for (int ni = 0; ni < 8; ni++) {
                int br = brow_base + ni * 8;
                bf[ni][0] = lds32(stB + sw128((uint32_t)(br * 128 + kb)));
                bf[ni][1] = lds32(stB + sw128((uint32_t)(br * 128 + kb + 16)));
            }
            // A: fp32 subtile (sub = ks>>1), pack to half2 in-loop
            const uint32_t aS = stA + (ks >> 1) * A_SUB;
            const int kp = (ks & 1) * 16 + klane2;           // fp32 elem within subtile
            #pragma unroll
            for (int mi = 0; mi < 2; mi++) {
                int ar = arow_base + mi * 16;
                float f0, f1;
                uint32_t af[4];
                lds_v2f(f0, f1, aS + sw128((uint32_t)(ar * 128 + kp * 4)));
                af[0] = packh2(f0, f1);
                lds_v2f(f0, f1, aS + sw128((uint32_t)((ar + 8) * 128 + kp * 4)));
                af[1] = packh2(f0, f1);
                lds_v2f(f0, f1, aS + sw128((uint32_t)(ar * 128 + (kp + 8) * 4)));
                af[2] = packh2(f0, f1);
                lds_v2f(f0, f1, aS + sw128((uint32_t)((ar + 8) * 128 + (kp + 8) * 4)));
                af[3] = packh2(f0, f1);
                #pragma unroll
                for (int ni = 0; ni < 8; ni++) mma_f16(acc[mi][ni], af, bf[ni]);
            }
        }
        __syncthreads();
        if (kt + NST - 1 < KT) load_stage(kt + NST - 1);
    }

    // ---------------- epilogue ----------------
    if (EPI == 0) {
        // scale by dis_j, write g_Mrow directly and g_Mth via SMEM transpose.
        __syncthreads();                      // smem tiles now dead — reuse
        __half* sC = reinterpret_cast<__half*>(smem);
        constexpr int PITCH = 136;            // halves; 272B rows (16B-aligned)
        #pragma unroll
        for (int mi = 0; mi < 2; mi++) {
            const int r0 = wm * 32 + mi * 16 + (lane >> 2);
            const size_t j0 = mrow0 + r0;
            const float dis0 = g_dis[j0], dis1 = g_dis[j0 + 8];
            #pragma unroll
            for (int ni = 0; ni < 8; ni++) {
                const int n = wn * 64 + ni * 8 + (lane & 3) * 2;   // local n
                uint32_t p0 = packh2(dis0 * acc[mi][ni][0], dis0 * acc[mi][ni][1]);
                uint32_t p1 = packh2(dis1 * acc[mi][ni][2], dis1 * acc[mi][ni][3]);
                *reinterpret_cast<uint32_t*>(g_Mrow + j0 * DIM + nrow0 + n)       = p0;
                *reinterpret_cast<uint32_t*>(g_Mrow + (j0 + 8) * DIM + nrow0 + n) = p1;
                __half2 h0 = *reinterpret_cast<__half2*>(&p0);
                __half2 h1 = *reinterpret_cast<__half2*>(&p1);
                sC[n * PITCH + r0]           = __low2half(h0);
                sC[(n + 1) * PITCH + r0]     = __high2half(h0);
                sC[n * PITCH + r0 + 8]       = __low2half(h1);
                sC[(n + 1) * PITCH + r0 + 8] = __high2half(h1);
            }
        }
        __syncthreads();
        // 256 threads: n = tid>>1 (128 rows), seg = tid&1 -> 64 halves each
        const int n = tid >> 1, seg = tid & 1;
        const __half* src = sC + n * PITCH + seg * 64;
        __half* dst = g_Mth + (nrow0 + n) * (size_t)NN + mrow0 + seg * 64;
        #pragma unroll
        for (int w = 0; w < 8; w++)     // 8 x 16B = 64 halves (was 4 — the bug)
            reinterpret_cast<uint4*>(dst)[w] = reinterpret_cast<const uint4*>(src)[w];
    } else {
        #pragma unroll
        for (int mi = 0; mi < 2; mi++) {
            const int r0 = wm * 32 + mi * 16 + (lane >> 2);
            const size_t i0 = mrow0 + r0;
            const float dis0 = g_dis[i0], dis1 = g_dis[i0 + 8];
            #pragma unroll
            for (int ni = 0; ni < 8; ni++) {
                const int n = (int)nrow0 + wn * 64 + ni * 8 + (lane & 3) * 2;
                const float b0 = bias[n], b1 = bias[n + 1];
                __half2 mh0 = *reinterpret_cast<const __half2*>(g_Mrow + i0 * DIM + n);
                __half2 mh1 = *reinterpret_cast<const __half2*>(g_Mrow + (i0 + 8) * DIM + n);
                float2 mf0 = __half22float2(mh0);
                float2 mf1 = __half22float2(mh1);
                float v0 = dis0 * (acc[mi][ni][0] + mf0.x) + b0;
                float v1 = dis0 * (acc[mi][ni][1] + mf0.y) + b1;
                float v2 = dis1 * (acc[mi][ni][2] + mf1.x) + b0;
                float v3 = dis1 * (acc[mi][ni][3] + mf1.y) + b1;
                float2 p0 = make_float2(v0 > 0.f ? v0 : 0.f, v1 > 0.f ? v1 : 0.f);
                float2 p1 = make_float2(v2 > 0.f ? v2 : 0.f, v3 > 0.f ? v3 : 0.f);
                *reinterpret_cast<float2*>(out + i0 * DIM + n)       = p0;
                *reinterpret_cast<float2*>(out + (i0 + 8) * DIM + n) = p1;
            }
        }
    }
}

// ---------------- launch ----------------
extern "C" void kernel_launch(void* const* d_in, const int* in_sizes, int n_in,
                              void* d_out, int out_size) {
    const float* x   = (const float*)d_in[0];
    const float* adj = (const float*)d_in[1];
    const float* W   = (const float*)d_in[2];
    const float* b   = (const float*)d_in[3];
    float* out = (float*)d_out;

    cudaFuncSetAttribute(gemm_k<0>, cudaFuncAttributeMaxDynamicSharedMemorySize, DSMEM);
    cudaFuncSetAttribute(gemm_k<1>, cudaFuncAttributeMaxDynamicSharedMemorySize, DSMEM);

    prep_w_kernel<<<DIM, DIM>>>(W);
    degree_kernel<<<NN, 256>>>(adj);
    gemm_k<0><<<dim3(NN / 128, 2), 256, DSMEM>>>(x, DIM, DIM / 64, nullptr, nullptr);
    gemm_k<1><<<dim3(NN / 128, 2), 256, DSMEM>>>(adj, NN, NN / 64, b, out);
}

// round 9
// speedup vs baseline: 1.1074x; 1.1074x over previous
#include <cuda_runtime.h>
#include <cuda_fp16.h>
#include <cstdint>

#define DI __device__ __forceinline__

static constexpr int NN  = 8192;
static constexpr int DIM = 256;

// ---------------- scratch (device globals; allocation forbidden) -----------
__device__ __align__(1024) float  g_dis[NN];                // rsqrt(1 + rowsum(adj))
__device__ __align__(1024) __half g_Mth[(size_t)DIM * NN];  // M^T [n][j] fp16 (B layout)
__device__ __align__(1024) __half g_Mrow[(size_t)NN * DIM]; // M   [j][n] fp16 (epilogue)
__device__ __align__(1024) __half g_Wh[DIM * DIM];          // W^T fp16

// ---------------- helpers ----------------
DI uint32_t h2_u32(__half2 h) { return *reinterpret_cast<uint32_t*>(&h); }
DI uint32_t packh2(float f0, float f1) {
    __half2 h = __floats2half2_rn(f0, f1);
    return h2_u32(h);
}
DI uint32_t smem_u32(const void* p) {
    uint32_t a;
    asm("{ .reg .u64 t; cvta.to.shared.u64 t, %1; cvt.u32.u64 %0, t; }" : "=r"(a) : "l"(p));
    return a;
}
DI void cp16(uint32_t s, const void* g) {
    asm volatile("cp.async.cg.shared.global [%0], [%1], 16;" :: "r"(s), "l"(g) : "memory");
}
DI void cp_commit() { asm volatile("cp.async.commit_group;" ::: "memory"); }
template <int N> DI void cp_wait() {
    asm volatile("cp.async.wait_group %0;" :: "n"(N) : "memory");
}
DI uint32_t lds32(uint32_t a) {
    uint32_t v;
    asm volatile("ld.shared.b32 %0, [%1];" : "=r"(v) : "r"(a));
    return v;
}
DI void sts64(uint32_t a, uint32_t v0, uint32_t v1) {
    asm volatile("st.shared.v2.b32 [%0], {%1,%2};" :: "r"(a), "r"(v0), "r"(v1) : "memory");
}
DI void mma_f16(float* d, const uint32_t* a, const uint32_t* b) {
    asm volatile(
        "mma.sync.aligned.m16n8k16.row.col.f32.f16.f16.f32 "
        "{%0,%1,%2,%3}, {%4,%5,%6,%7}, {%8,%9}, {%0,%1,%2,%3};"
        : "+f"(d[0]), "+f"(d[1]), "+f"(d[2]), "+f"(d[3])
        : "r"(a[0]), "r"(a[1]), "r"(a[2]), "r"(a[3]), "r"(b[0]), "r"(b[1]));
}
DI uint32_t sw128(uint32_t off) { return off ^ ((off >> 3) & 0x70); }

// ---------------- SMEM layout ----------------
// Per stage: fp16 A tile 128x64 (128B rows, SW128) 16 KB + fp16 B tile 16 KB.
static constexpr int NST     = 4;
static constexpr int T_BYTES = 128 * 128;          // 16 KB
static constexpr int STAGE   = 2 * T_BYTES;        // 32 KB
static constexpr int DSMEM   = NST * STAGE;        // 128 KB

// ------ degree: g_dis[i] = rsqrt(1 + rowsum(adj)) (read-only) --------------
__global__ void __launch_bounds__(256) degree_kernel(const float* __restrict__ adj) {
    const int i = blockIdx.x;
    const float4* row = reinterpret_cast<const float4*>(adj + (size_t)i * NN);
    float s = 0.f;
    for (int t = threadIdx.x; t < NN / 4; t += 256) {
        float4 v = row[t];
        s += (v.x + v.y) + (v.z + v.w);
    }
    for (int off = 16; off > 0; off >>= 1) s += __shfl_xor_sync(0xFFFFFFFFu, s, off);
    __shared__ float ws[8];
    if ((threadIdx.x & 31) == 0) ws[threadIdx.x >> 5] = s;
    __syncthreads();
    if (threadIdx.x == 0) {
        float t = 0.f;
        #pragma unroll
        for (int k = 0; k < 8; k++) t += ws[k];
        g_dis[i] = rsqrtf(t + 1.0f);
    }
}

// ---------------- prep: W^T -> fp16 ----------------------------------------
__global__ void __launch_bounds__(256) prep_w_kernel(const float* __restrict__ W) {
    int n = blockIdx.x, k = threadIdx.x;
    g_Wh[n * DIM + k] = __float2half_rn(W[k * DIM + n]);
}

// ---- fp16 mma GEMM; A is fp32 in GMEM, converted on the LDG->STS path -----
// 512 threads, warp grid 4(M) x 4(N), warp tile 32x32, CTA tile 128x128.
// EPI=0: A=x (lda=256, KT=4),     B=g_Wh.  C -> g_Mth (smem transpose) + g_Mrow
// EPI=1: A=adj (lda=8192, KT=128), B=g_Mth. C -> out=relu(dis_i*(acc+M[i][n])+b[n])
template <int EPI>
__global__ void __launch_bounds__(512, 1)
gemm_k(const float* __restrict__ A, int lda, int KT,
       const float* __restrict__ bias, float* __restrict__ out) {
    const __half* __restrict__ B = EPI ? (const __half*)g_Mth : (const __half*)g_Wh;
    const int ldb = EPI ? NN : DIM;

    extern __shared__ char smem[];
    const uint32_t sb = smem_u32(smem);
    const int tid = threadIdx.x, lane = tid & 31, wid = tid >> 5;
    const int wm = wid & 3, wn = wid >> 2;          // 4(M) x 4(N)
    const size_t mrow0 = (size_t)blockIdx.x * 128;
    const size_t nrow0 = (size_t)blockIdx.y * 128;

    float acc[2][4][4];
    #pragma unroll
    for (int mi = 0; mi < 2; mi++)
        #pragma unroll
        for (int ni = 0; ni < 4; ni++)
            #pragma unroll
            for (int r = 0; r < 4; r++) acc[mi][ni][r] = 0.f;

    // ---- A loader (LDG fp32 -> cvt -> STS fp16) geometry ----
    // tile 128 rows x 16 float4 cols; thread: row = tid>>4 (+32 per q), f4col = tid&15
    const int arow = tid >> 4, af4 = tid & 15;
    const float4* gA = reinterpret_cast<const float4*>(
        A + (mrow0 + arow) * (size_t)lda + af4 * 4);
    const size_t stepA4 = 32ull * (size_t)lda / 4;          // +32 rows, in float4
    const uint32_t asts = sw128((uint32_t)(arow * 128 + af4 * 8));  // 8B dest

    // ---- B cp.async geometry: 1024 x 16B chunks, 2 per thread ----
    const int bc = tid;                                     // + q*512
    const int brow_c = bc >> 3, bseg = bc & 7;
    const uint32_t bdst = sw128((uint32_t)(brow_c * 128 + bseg * 16));
    const __half* gB = B + (nrow0 + brow_c) * (size_t)ldb + bseg * 8;
    const size_t stepB = 64ull * (size_t)ldb;               // +64 rows (q stride)

    float4 apf[4];
    auto ldgA = [&](int kt) {
        const int kq = kt * 16;                             // 64 floats = 16 float4
        #pragma unroll
        for (int q = 0; q < 4; q++) apf[q] = gA[kq + q * stepA4];
    };
    auto stsA = [&](int kt) {
        const uint32_t stA = sb + (kt & (NST - 1)) * STAGE;
        #pragma unroll
        for (int q = 0; q < 4; q++) {
            uint32_t h0 = packh2(apf[q].x, apf[q].y);
            uint32_t h1 = packh2(apf[q].z, apf[q].w);
            sts64(stA + asts + q * (32 * 128), h0, h1);
        }
    };
    auto cpB = [&](int kt) {
        const uint32_t stB = sb + (kt & (NST - 1)) * STAGE + T_BYTES;
        const int k0 = kt * 64;
        #pragma unroll
        for (int q = 0; q < 2; q++)
            cp16(stB + bdst + q * (64 * 128), gB + k0 + q * stepB);
    };

    // ---- prologue ----
    ldgA(0); stsA(0);
    if (KT > 1) ldgA(1);
    cpB(0); cp_commit();
    if (KT > 1) cpB(1); cp_commit();
    if (KT > 2) cpB(2); cp_commit();

    // fragment geometry (m16n8k16, fp16, 128B SW128 rows)
    const int arow_base = wm * 32 + (lane >> 2);     // + mi*16, +8
    const int brow_base = wn * 32 + (lane >> 2);     // + ni*8
    const int kbl = (lane & 3) * 4;                  // byte col base

    for (int kt = 0; kt < KT; kt++) {
        cp_wait<2>();
        __syncthreads();
        // write next A stage (regs -> fp16 smem), prefetch following A, next B
        if (kt + 1 < KT) stsA(kt + 1);
        if (kt + 2 < KT) ldgA(kt + 2);
        if (kt + 3 < KT) cpB(kt + 3);
        cp_commit();                                  // uniform group count

        const uint32_t stA = sb + (kt & (NST - 1)) * STAGE;
        const uint32_t stB = stA + T_BYTES;

        #pragma unroll
        for (int ks = 0; ks < 4; ks++) {
            const int kb = ks * 32 + kbl;
            uint32_t bf[4][2];
            #pragma unroll
            for (int ni = 0; ni < 4; ni++) {
                int br = brow_base + ni * 8;
                bf[ni][0] = lds32(stB + sw128((uint32_t)(br * 128 + kb)));
                bf[ni][1] = lds32(stB + sw128((uint32_t)(br * 128 + kb + 16)));
            }
            #pragma unroll
            for (int mi = 0; mi < 2; mi++) {
                int ar = arow_base + mi * 16;
                uint32_t af[4];
                af[0] = lds32(stA + sw128((uint32_t)(ar * 128 + kb)));
                af[1] = lds32(stA + sw128((uint32_t)((ar + 8) * 128 + kb)));
                af[2] = lds32(stA + sw128((uint32_t)(ar * 128 + kb + 16)));
                af[3] = lds32(stA + sw128((uint32_t)((ar + 8) * 128 + kb + 16)));
                #pragma unroll
                for (int ni = 0; ni < 4; ni++) mma_f16(acc[mi][ni], af, bf[ni]);
            }
        }
    }

    // ---------------- epilogue ----------------
    if (EPI == 0) {
        __syncthreads();                      // pipeline smem dead — reuse
        __half* sC = reinterpret_cast<__half*>(smem);
        constexpr int PITCH = 136;            // halves; 272 B rows
        #pragma unroll
        for (int mi = 0; mi < 2; mi++) {
            const int r0 = wm * 32 + mi * 16 + (lane >> 2);
            const size_t j0 = mrow0 + r0;
            const float dis0 = g_dis[j0], dis1 = g_dis[j0 + 8];
            #pragma unroll
            for (int ni = 0; ni < 4; ni++) {
                const int n = wn * 32 + ni * 8 + (lane & 3) * 2;   // local n
                uint32_t p0 = packh2(dis0 * acc[mi][ni][0], dis0 * acc[mi][ni][1]);
                uint32_t p1 = packh2(dis1 * acc[mi][ni][2], dis1 * acc[mi][ni][3]);
                *reinterpret_cast<uint32_t*>(g_Mrow + j0 * DIM + nrow0 + n)       = p0;
                *reinterpret_cast<uint32_t*>(g_Mrow + (j0 + 8) * DIM + nrow0 + n) = p1;
                __half2 h0 = *reinterpret_cast<__half2*>(&p0);
                __half2 h1 = *reinterpret_cast<__half2*>(&p1);
                sC[n * PITCH + r0]           = __low2half(h0);
                sC[(n + 1) * PITCH + r0]     = __high2half(h0);
                sC[n * PITCH + r0 + 8]       = __low2half(h1);
                sC[(n + 1) * PITCH + r0 + 8] = __high2half(h1);
            }
        }
        __syncthreads();
        // 512 threads: n = tid>>2 (128 rows), seg = tid&3 -> 32 halves each
        const int n = tid >> 2, seg = tid & 3;
        const __half* src = sC + n * PITCH + seg * 32;
        __half* dst = g_Mth + (nrow0 + n) * (size_t)NN + mrow0 + seg * 32;
        #pragma unroll
        for (int w = 0; w < 4; w++)
            reinterpret_cast<uint4*>(dst)[w] = reinterpret_cast<const uint4*>(src)[w];
    } else {
        #pragma unroll
        for (int mi = 0; mi < 2; mi++) {
            const int r0 = wm * 32 + mi * 16 + (lane >> 2);
            const size_t i0 = mrow0 + r0;
            const float dis0 = g_dis[i0], dis1 = g_dis[i0 + 8];
            #pragma unroll
            for (int ni = 0; ni < 4; ni++) {
                const int n = (int)nrow0 + wn * 32 + ni * 8 + (lane & 3) * 2;
                const float b0 = bias[n], b1 = bias[n + 1];
                __half2 mh0 = *reinterpret_cast<const __half2*>(g_Mrow + i0 * DIM + n);
                __half2 mh1 = *reinterpret_cast<const __half2*>(g_Mrow + (i0 + 8) * DIM + n);
                float2 mf0 = __half22float2(mh0);
                float2 mf1 = __half22float2(mh1);
                float v0 = dis0 * (acc[mi][ni][0] + mf0.x) + b0;
                float v1 = dis0 * (acc[mi][ni][1] + mf0.y) + b1;
                float v2 = dis1 * (acc[mi][ni][2] + mf1.x) + b0;
                float v3 = dis1 * (acc[mi][ni][3] + mf1.y) + b1;
                float2 p0 = make_float2(v0 > 0.f ? v0 : 0.f, v1 > 0.f ? v1 : 0.f);
                float2 p1 = make_float2(v2 > 0.f ? v2 : 0.f, v3 > 0.f ? v3 : 0.f);
                *reinterpret_cast<float2*>(out + i0 * DIM + n)       = p0;
                *reinterpret_cast<float2*>(out + (i0 + 8) * DIM + n) = p1;
            }
        }
    }
}

// ---------------- launch ----------------
extern "C" void kernel_launch(void* const* d_in, const int* in_sizes, int n_in,
                              void* d_out, int out_size) {
    const float* x   = (const float*)d_in[0];
    const float* adj = (const float*)d_in[1];
    const float* W   = (const float*)d_in[2];
    const float* b   = (const float*)d_in[3];
    float* out = (float*)d_out;

    cudaFuncSetAttribute(gemm_k<0>, cudaFuncAttributeMaxDynamicSharedMemorySize, DSMEM);
    cudaFuncSetAttribute(gemm_k<1>, cudaFuncAttributeMaxDynamicSharedMemorySize, DSMEM);

    prep_w_kernel<<<DIM, DIM>>>(W);
    degree_kernel<<<NN, 256>>>(adj);
    gemm_k<0><<<dim3(NN / 128, 2), 512, DSMEM>>>(x, DIM, DIM / 64, nullptr, nullptr);
    gemm_k<1><<<dim3(NN / 128, 2), 512, DSMEM>>>(adj, NN, NN / 64, b, out);
}